// round 2
// baseline (speedup 1.0000x reference)
#include <cuda_runtime.h>
#include <math.h>

#define BATCH 16
#define NSEQ  2048
#define DIM   256
#define TQ    64
#define TK    64
#define THREADS 256

// Shared memory layout (floats):
//  Qs[256][64]   transposed Q tile (d-major)      16384
//  Kt[256][64]   transposed K tile (d-major)      16384
//  Vs[64][260]   row-major V tile (j, d) +pad     16640
//  Ps[64][68]    P tile (k-major, q contiguous)    4352
#define QS_OFF 0
#define KT_OFF (256*64)
#define VS_OFF (KT_OFF + 256*64)
#define VS_STRIDE 260
#define PS_OFF (VS_OFF + 64*VS_STRIDE)
#define PS_STRIDE 68
#define SMEM_FLOATS (PS_OFF + 64*PS_STRIDE)

__global__ __launch_bounds__(THREADS, 1)
void attn_fp32_flash(const float* __restrict__ X,
                     const int* __restrict__ length,
                     float* __restrict__ out)
{
    extern __shared__ float smem[];
    float* Qs = smem + QS_OFF;
    float* Kt = smem + KT_OFF;
    float* Vs = smem + VS_OFF;
    float* Ps = smem + PS_OFF;

    const int qt = blockIdx.x;       // 0..31
    const int b  = blockIdx.y;       // 0..15
    const int tid = threadIdx.x;
    const int tx = tid & 15;         // key group / d group
    const int ty = tid >> 4;         // query group (same mapping in both GEMMs)

    const float* Xb = X + (size_t)b * NSEQ * DIM;
    const int q0g = qt * TQ;
    int len = length[b];
    if (len < 1) len = 1;
    if (len > NSEQ) len = NSEQ;      // defensive clamp: never walk past X
    const int numKT = (len + (TK - 1)) / TK;   // skip fully-masked tiles

    // ---- load Q tile, transposed: Qs[d][q] ----
    {
        const int q  = tid & 63;
        const int dq = tid >> 6;     // 0..3
        #pragma unroll
        for (int it = 0; it < 16; ++it) {
            const int dvec = dq + 4 * it;     // 0..63
            const int d0 = dvec * 4;
            float4 v = *(const float4*)(Xb + (size_t)(q0g + q) * DIM + d0);
            Qs[(d0 + 0) * 64 + q] = v.x;
            Qs[(d0 + 1) * 64 + q] = v.y;
            Qs[(d0 + 2) * 64 + q] = v.z;
            Qs[(d0 + 3) * 64 + q] = v.w;
        }
    }

    const int qb = ty * 4;           // this thread's 4 queries (both phases)
    const int kb = tx * 4;           // this thread's 4 keys (score phase)
    const int db = tx * 16;          // this thread's 16 d-columns (PV phase)

    float acc[64];                   // [qi][dd] output accumulators
    #pragma unroll
    for (int i = 0; i < 64; ++i) acc[i] = 0.0f;
    float m[4], l[4];
    #pragma unroll
    for (int i = 0; i < 4; ++i) { m[i] = -1e30f; l[i] = 0.0f; }

    for (int kt = 0; kt < numKT; ++kt) {
        const int k0g = kt * TK;
        __syncthreads();   // previous PV done with Vs/Ps

        // ---- load K tile transposed: Kt[d][k] ----
        {
            const int k  = tid & 63;
            const int dq = tid >> 6;
            #pragma unroll
            for (int it = 0; it < 16; ++it) {
                const int d0 = (dq + 4 * it) * 4;
                float4 v = *(const float4*)(Xb + (size_t)(k0g + k) * DIM + d0);
                Kt[(d0 + 0) * 64 + k] = v.x;
                Kt[(d0 + 1) * 64 + k] = v.y;
                Kt[(d0 + 2) * 64 + k] = v.z;
                Kt[(d0 + 3) * 64 + k] = v.w;
            }
        }
        // ---- load V tile row-major: Vs[j][d] ----
        {
            const int c4 = tid & 63;     // d-quad 0..63
            const int jb = tid >> 6;     // 0..3
            #pragma unroll
            for (int it = 0; it < 16; ++it) {
                const int j = jb + 4 * it;
                float4 v = *(const float4*)(Xb + (size_t)(k0g + j) * DIM + c4 * 4);
                *(float4*)(Vs + j * VS_STRIDE + c4 * 4) = v;
            }
        }
        __syncthreads();

        // ---- score GEMM: s[4][4] = Q[qb..][:] . K[kb..][:] ----
        float s[4][4];
        #pragma unroll
        for (int i = 0; i < 4; ++i)
            #pragma unroll
            for (int j = 0; j < 4; ++j) s[i][j] = 0.0f;

        #pragma unroll 8
        for (int d = 0; d < DIM; ++d) {
            float4 qv = *(const float4*)(Qs + d * 64 + qb);
            float4 kv = *(const float4*)(Kt + d * 64 + kb);
            s[0][0] += qv.x * kv.x; s[0][1] += qv.x * kv.y; s[0][2] += qv.x * kv.z; s[0][3] += qv.x * kv.w;
            s[1][0] += qv.y * kv.x; s[1][1] += qv.y * kv.y; s[1][2] += qv.y * kv.z; s[1][3] += qv.y * kv.w;
            s[2][0] += qv.z * kv.x; s[2][1] += qv.z * kv.y; s[2][2] += qv.z * kv.z; s[2][3] += qv.z * kv.w;
            s[3][0] += qv.w * kv.x; s[3][1] += qv.w * kv.y; s[3][2] += qv.w * kv.z; s[3][3] += qv.w * kv.w;
        }

        // ---- mask columns past length ----
        #pragma unroll
        for (int kj = 0; kj < 4; ++kj) {
            const int kg = k0g + kb + kj;
            if (kg >= len) {
                #pragma unroll
                for (int qi = 0; qi < 4; ++qi) s[qi][kj] = -1e30f;
            }
        }

        // ---- online softmax update ----
        float scale[4], mn[4];
        #pragma unroll
        for (int qi = 0; qi < 4; ++qi) {
            float tm = fmaxf(fmaxf(s[qi][0], s[qi][1]), fmaxf(s[qi][2], s[qi][3]));
            // reduce over the 16 tx-threads sharing these queries
            tm = fmaxf(tm, __shfl_xor_sync(0xffffffffu, tm, 1));
            tm = fmaxf(tm, __shfl_xor_sync(0xffffffffu, tm, 2));
            tm = fmaxf(tm, __shfl_xor_sync(0xffffffffu, tm, 4));
            tm = fmaxf(tm, __shfl_xor_sync(0xffffffffu, tm, 8));
            mn[qi] = fmaxf(m[qi], tm);
            scale[qi] = __expf(m[qi] - mn[qi]);
            m[qi] = mn[qi];
        }
        #pragma unroll
        for (int qi = 0; qi < 4; ++qi) {
            float r = 0.0f;
            #pragma unroll
            for (int kj = 0; kj < 4; ++kj) {
                s[qi][kj] = __expf(s[qi][kj] - mn[qi]);
                r += s[qi][kj];
            }
            r += __shfl_xor_sync(0xffffffffu, r, 1);
            r += __shfl_xor_sync(0xffffffffu, r, 2);
            r += __shfl_xor_sync(0xffffffffu, r, 4);
            r += __shfl_xor_sync(0xffffffffu, r, 8);
            l[qi] = l[qi] * scale[qi] + r;
        }
        // rescale accumulators
        #pragma unroll
        for (int qi = 0; qi < 4; ++qi) {
            #pragma unroll
            for (int dd = 0; dd < 16; ++dd) acc[qi * 16 + dd] *= scale[qi];
        }
        // write P (k-major, q contiguous)
        #pragma unroll
        for (int kj = 0; kj < 4; ++kj) {
            float4 pv = make_float4(s[0][kj], s[1][kj], s[2][kj], s[3][kj]);
            *(float4*)(Ps + (kb + kj) * PS_STRIDE + qb) = pv;
        }
        __syncthreads();

        // ---- PV GEMM: acc[qi][dd] += P[q][j] * V[j][d] ----
        #pragma unroll 2
        for (int j = 0; j < TK; ++j) {
            float4 pv = *(const float4*)(Ps + j * PS_STRIDE + qb);
            const float* vrow = Vs + j * VS_STRIDE + db;
            float4 v0 = *(const float4*)(vrow + 0);
            float4 v1 = *(const float4*)(vrow + 4);
            float4 v2 = *(const float4*)(vrow + 8);
            float4 v3 = *(const float4*)(vrow + 12);
            const float p0 = pv.x, p1 = pv.y, p2 = pv.z, p3 = pv.w;
            acc[ 0] += p0 * v0.x; acc[ 1] += p0 * v0.y; acc[ 2] += p0 * v0.z; acc[ 3] += p0 * v0.w;
            acc[ 4] += p0 * v1.x; acc[ 5] += p0 * v1.y; acc[ 6] += p0 * v1.z; acc[ 7] += p0 * v1.w;
            acc[ 8] += p0 * v2.x; acc[ 9] += p0 * v2.y; acc[10] += p0 * v2.z; acc[11] += p0 * v2.w;
            acc[12] += p0 * v3.x; acc[13] += p0 * v3.y; acc[14] += p0 * v3.z; acc[15] += p0 * v3.w;
            acc[16] += p1 * v0.x; acc[17] += p1 * v0.y; acc[18] += p1 * v0.z; acc[19] += p1 * v0.w;
            acc[20] += p1 * v1.x; acc[21] += p1 * v1.y; acc[22] += p1 * v1.z; acc[23] += p1 * v1.w;
            acc[24] += p1 * v2.x; acc[25] += p1 * v2.y; acc[26] += p1 * v2.z; acc[27] += p1 * v2.w;
            acc[28] += p1 * v3.x; acc[29] += p1 * v3.y; acc[30] += p1 * v3.z; acc[31] += p1 * v3.w;
            acc[32] += p2 * v0.x; acc[33] += p2 * v0.y; acc[34] += p2 * v0.z; acc[35] += p2 * v0.w;
            acc[36] += p2 * v1.x; acc[37] += p2 * v1.y; acc[38] += p2 * v1.z; acc[39] += p2 * v1.w;
            acc[40] += p2 * v2.x; acc[41] += p2 * v2.y; acc[42] += p2 * v2.z; acc[43] += p2 * v2.w;
            acc[44] += p2 * v3.x; acc[45] += p2 * v3.y; acc[46] += p2 * v3.z; acc[47] += p2 * v3.w;
            acc[48] += p3 * v0.x; acc[49] += p3 * v0.y; acc[50] += p3 * v0.z; acc[51] += p3 * v0.w;
            acc[52] += p3 * v1.x; acc[53] += p3 * v1.y; acc[54] += p3 * v1.z; acc[55] += p3 * v1.w;
            acc[56] += p3 * v2.x; acc[57] += p3 * v2.y; acc[58] += p3 * v2.z; acc[59] += p3 * v2.w;
            acc[60] += p3 * v3.x; acc[61] += p3 * v3.y; acc[62] += p3 * v3.z; acc[63] += p3 * v3.w;
        }
    }

    // ---- normalize and store ----
    float* Ob = out + (size_t)b * NSEQ * DIM;
    #pragma unroll
    for (int qi = 0; qi < 4; ++qi) {
        const float inv = 1.0f / l[qi];
        float* orow = Ob + (size_t)(q0g + qb + qi) * DIM + db;
        #pragma unroll
        for (int c = 0; c < 4; ++c) {
            float4 o;
            o.x = acc[qi * 16 + c * 4 + 0] * inv;
            o.y = acc[qi * 16 + c * 4 + 1] * inv;
            o.z = acc[qi * 16 + c * 4 + 2] * inv;
            o.w = acc[qi * 16 + c * 4 + 3] * inv;
            *(float4*)(orow + c * 4) = o;
        }
    }
}

extern "C" void kernel_launch(void* const* d_in, const int* in_sizes, int n_in,
                              void* d_out, int out_size)
{
    (void)in_sizes; (void)n_in; (void)out_size;
    const float* X = (const float*)d_in[0];
    const int* len = (const int*)d_in[1];
    float* out = (float*)d_out;

    const size_t smem_bytes = (size_t)SMEM_FLOATS * sizeof(float);  // 215040
    cudaFuncSetAttribute(attn_fp32_flash,
                         cudaFuncAttributeMaxDynamicSharedMemorySize,
                         (int)smem_bytes);

    dim3 grid(NSEQ / TQ, BATCH);   // (32, 16)
    attn_fp32_flash<<<grid, THREADS, smem_bytes>>>(X, len, out);
}

// round 4
// speedup vs baseline: 3.6208x; 3.6208x over previous
#include <cuda_runtime.h>
#include <cuda_fp16.h>
#include <cstdint>

#define BATCH 16
#define NSEQ  2048
#define DIM   256
#define TQ    64
#define TK    64
#define THREADS 256

#define RS 264        // Q/K tile row stride (halfs): 528B, conflict-free for ldmatrix
#define PSTR 72       // P tile row stride (halfs): 144B

// ---- smem byte offsets ----
#define SM_QHI 0
#define SM_QLO (SM_QHI + TQ*RS*2)          // 33792
#define SM_KHI (SM_QLO + TQ*RS*2)          // 67584
#define SM_KLO (SM_KHI + TK*RS*2)          // 101376
#define SM_P   (SM_KLO + TK*RS*2)          // 135168
#define PBYTES (16*PSTR*2)                 // 2304 per (group, hi|lo)
#define SM_STATS (SM_P + 4*2*PBYTES)       // 153600 ; max[4][2][16] f32, sum at +512
#define SM_TOTAL (SM_STATS + 1024)         // 154624

__device__ __forceinline__ uint32_t smem_u32(const void* p) {
    uint32_t a;
    asm("{ .reg .u64 t; cvta.to.shared.u64 t, %1; cvt.u32.u64 %0, t; }" : "=r"(a) : "l"(p));
    return a;
}
__device__ __forceinline__ void ldsm_x4(uint32_t& r0, uint32_t& r1, uint32_t& r2, uint32_t& r3, uint32_t a) {
    asm volatile("ldmatrix.sync.aligned.m8n8.x4.shared.b16 {%0,%1,%2,%3}, [%4];"
                 : "=r"(r0), "=r"(r1), "=r"(r2), "=r"(r3) : "r"(a));
}
__device__ __forceinline__ void ldsm_x4t(uint32_t& r0, uint32_t& r1, uint32_t& r2, uint32_t& r3, uint32_t a) {
    asm volatile("ldmatrix.sync.aligned.m8n8.x4.trans.shared.b16 {%0,%1,%2,%3}, [%4];"
                 : "=r"(r0), "=r"(r1), "=r"(r2), "=r"(r3) : "r"(a));
}
__device__ __forceinline__ void mma16816(float* d, const uint32_t* a, uint32_t b0, uint32_t b1) {
    asm volatile("mma.sync.aligned.m16n8k16.row.col.f32.f16.f16.f32 "
                 "{%0,%1,%2,%3}, {%4,%5,%6,%7}, {%8,%9}, {%0,%1,%2,%3};"
                 : "+f"(d[0]), "+f"(d[1]), "+f"(d[2]), "+f"(d[3])
                 : "r"(a[0]), "r"(a[1]), "r"(a[2]), "r"(a[3]), "r"(b0), "r"(b1));
}
__device__ __forceinline__ uint32_t hpack(float x, float y) {
    __half2 h = __floats2half2_rn(x, y);
    return *(uint32_t*)&h;
}
__device__ __forceinline__ void hsplit2(float x, float y, uint32_t& hi, uint32_t& lo) {
    __half hx = __float2half_rn(x), hy = __float2half_rn(y);
    float lx = x - __half2float(hx), ly = y - __half2float(hy);
    __half2 h = __halves2half2(hx, hy);
    hi = *(uint32_t*)&h;
    lo = hpack(lx, ly);
}

__global__ __launch_bounds__(THREADS, 1)
void attn_hmma(const float* __restrict__ X,
               const int* __restrict__ length,
               float* __restrict__ out)
{
    extern __shared__ char smem[];
    const uint32_t sb = smem_u32(smem);
    const int tid  = threadIdx.x;
    const int wid  = tid >> 5;
    const int lane = tid & 31;
    const int g = wid >> 1;          // row group: q rows 16g..16g+15
    const int h = wid & 1;           // key-half (QK) / d-half (PV)

    const int qt = blockIdx.x;
    const int b  = blockIdx.y;
    const float* Xb = X + (size_t)b * NSEQ * DIM;
    const int q0g = qt * TQ;

    int len = length[b];
    if (len < 1) len = 1;
    if (len > NSEQ) len = NSEQ;
    const int numKT = (len + TK - 1) / TK;

    // ---- load Q tile (hi/lo split) ----
    {
        const int row = tid >> 2;
        const int db  = (tid & 3) * 64;
        const float4* src = (const float4*)(Xb + (size_t)(q0g + row) * DIM + db);
        uint32_t* qhi = (uint32_t*)(smem + SM_QHI);
        uint32_t* qlo = (uint32_t*)(smem + SM_QLO);
        #pragma unroll
        for (int c = 0; c < 16; ++c) {
            float4 v = src[c];
            const int idx = (row * RS + db + 4 * c) >> 1;   // u32 index
            uint32_t h0, l0, h1, l1;
            hsplit2(v.x, v.y, h0, l0);
            hsplit2(v.z, v.w, h1, l1);
            qhi[idx] = h0; qhi[idx + 1] = h1;
            qlo[idx] = l0; qlo[idx + 1] = l1;
        }
    }

    // ---- per-thread state ----
    float o[16][4];
    #pragma unroll
    for (int i = 0; i < 16; ++i)
        #pragma unroll
        for (int j = 0; j < 4; ++j) o[i][j] = 0.0f;
    float m0 = -1e30f, m1 = -1e30f, l0 = 0.0f, l1 = 0.0f;

    const int qr0 = g * 16;
    const int r   = lane >> 2;
    // ldmatrix base addresses
    const uint32_t qa_hi = sb + SM_QHI + (uint32_t)((qr0 + (lane & 15)) * RS) * 2 + (uint32_t)(lane >> 4) * 16;
    const uint32_t qa_lo = qa_hi + (SM_QLO - SM_QHI);
    const uint32_t bkey  = (uint32_t)(32 * h + ((lane >> 4) << 3) + (lane & 7));
    const uint32_t bdcol = (uint32_t)(((lane >> 3) & 1) * 8);
    const uint32_t kb_hi = sb + SM_KHI + (bkey * RS + bdcol) * 2;
    const uint32_t kb_lo = kb_hi + (SM_KLO - SM_KHI);
    const uint32_t pa_hi = sb + SM_P + (uint32_t)(g * 2 * PBYTES) + (uint32_t)((lane & 15) * PSTR) * 2 + (uint32_t)(lane >> 4) * 16;
    const uint32_t pa_lo = pa_hi + PBYTES;
    const uint32_t vkey  = (uint32_t)((lane & 7) + ((lane >> 3) & 1) * 8);
    const uint32_t vdcol = (uint32_t)(128 * h + (lane >> 4) * 8);
    const uint32_t vb_hi = sb + SM_KHI + (vkey * RS + vdcol) * 2;
    const uint32_t vb_lo = vb_hi + (SM_KLO - SM_KHI);
    float* stat_max = (float*)(smem + SM_STATS);
    float* stat_sum = (float*)(smem + SM_STATS + 512);

    for (int kt = 0; kt < numKT; ++kt) {
        __syncthreads();   // previous PV done reading K/P
        // ---- load K tile (hi/lo) ----
        {
            const int row = tid >> 2;
            const int db  = (tid & 3) * 64;
            const float4* src = (const float4*)(Xb + (size_t)(kt * TK + row) * DIM + db);
            uint32_t* khi = (uint32_t*)(smem + SM_KHI);
            uint32_t* klo = (uint32_t*)(smem + SM_KLO);
            #pragma unroll
            for (int c = 0; c < 16; ++c) {
                float4 v = src[c];
                const int idx = (row * RS + db + 4 * c) >> 1;
                uint32_t h0, lo0, h1, lo1;
                hsplit2(v.x, v.y, h0, lo0);
                hsplit2(v.z, v.w, h1, lo1);
                khi[idx] = h0; khi[idx + 1] = h1;
                klo[idx] = lo0; klo[idx + 1] = lo1;
            }
        }
        __syncthreads();

        // ---- QK: S(16 x 32h-half) = Qhi*Khi + Qhi*Klo + Qlo*Khi ----
        float s[4][4];
        #pragma unroll
        for (int i = 0; i < 4; ++i)
            #pragma unroll
            for (int j = 0; j < 4; ++j) s[i][j] = 0.0f;

        #pragma unroll
        for (int ks = 0; ks < 16; ++ks) {
            uint32_t ah[4], al[4];
            ldsm_x4(ah[0], ah[1], ah[2], ah[3], qa_hi + ks * 32);
            ldsm_x4(al[0], al[1], al[2], al[3], qa_lo + ks * 32);
            #pragma unroll
            for (int p = 0; p < 2; ++p) {
                const uint32_t boff = (uint32_t)(p * 16 * RS * 2 + ks * 32);
                uint32_t bh[4], bl[4];
                ldsm_x4(bh[0], bh[1], bh[2], bh[3], kb_hi + boff);
                ldsm_x4(bl[0], bl[1], bl[2], bl[3], kb_lo + boff);
                mma16816(s[2 * p],     ah, bh[0], bh[1]);
                mma16816(s[2 * p + 1], ah, bh[2], bh[3]);
                mma16816(s[2 * p],     ah, bl[0], bl[1]);
                mma16816(s[2 * p + 1], ah, bl[2], bl[3]);
                mma16816(s[2 * p],     al, bh[0], bh[1]);
                mma16816(s[2 * p + 1], al, bh[2], bh[3]);
            }
        }

        // ---- mask ----
        const int colbase = kt * TK + 32 * h + 2 * (lane & 3);
        #pragma unroll
        for (int n = 0; n < 4; ++n) {
            const int c0 = colbase + 8 * n;
            if (c0 >= len)     { s[n][0] = -1e30f; s[n][2] = -1e30f; }
            if (c0 + 1 >= len) { s[n][1] = -1e30f; s[n][3] = -1e30f; }
        }

        // ---- row max (quad + cross-warp) ----
        float mx0 = -1e30f, mx1 = -1e30f;
        #pragma unroll
        for (int n = 0; n < 4; ++n) {
            mx0 = fmaxf(mx0, fmaxf(s[n][0], s[n][1]));
            mx1 = fmaxf(mx1, fmaxf(s[n][2], s[n][3]));
        }
        mx0 = fmaxf(mx0, __shfl_xor_sync(0xffffffffu, mx0, 1));
        mx0 = fmaxf(mx0, __shfl_xor_sync(0xffffffffu, mx0, 2));
        mx1 = fmaxf(mx1, __shfl_xor_sync(0xffffffffu, mx1, 1));
        mx1 = fmaxf(mx1, __shfl_xor_sync(0xffffffffu, mx1, 2));
        if ((lane & 3) == 0) {
            stat_max[(g * 2 + h) * 16 + r]     = mx0;
            stat_max[(g * 2 + h) * 16 + r + 8] = mx1;
        }
        __syncthreads();
        {
            const float pm0 = stat_max[(g * 2 + (1 - h)) * 16 + r];
            const float pm1 = stat_max[(g * 2 + (1 - h)) * 16 + r + 8];
            mx0 = fmaxf(mx0, pm0);
            mx1 = fmaxf(mx1, pm1);
        }
        const float mn0 = fmaxf(m0, mx0);
        const float mn1 = fmaxf(m1, mx1);
        const float sc0 = __expf(m0 - mn0);
        const float sc1 = __expf(m1 - mn1);
        m0 = mn0; m1 = mn1;

        // ---- exp, sums, P write, O rescale ----
        float sm0 = 0.0f, sm1 = 0.0f;
        uint32_t* php = (uint32_t*)(smem + SM_P + g * 2 * PBYTES);
        uint32_t* plp = (uint32_t*)(smem + SM_P + g * 2 * PBYTES + PBYTES);
        #pragma unroll
        for (int n = 0; n < 4; ++n) {
            float p0 = __expf(s[n][0] - mn0);
            float p1 = __expf(s[n][1] - mn0);
            float p2 = __expf(s[n][2] - mn1);
            float p3 = __expf(s[n][3] - mn1);
            sm0 += p0 + p1;
            sm1 += p2 + p3;
            const int colL = 32 * h + 8 * n + 2 * (lane & 3);
            uint32_t hi, lo;
            hsplit2(p0, p1, hi, lo);
            php[(r * PSTR + colL) >> 1] = hi;
            plp[(r * PSTR + colL) >> 1] = lo;
            hsplit2(p2, p3, hi, lo);
            php[((r + 8) * PSTR + colL) >> 1] = hi;
            plp[((r + 8) * PSTR + colL) >> 1] = lo;
        }
        sm0 += __shfl_xor_sync(0xffffffffu, sm0, 1);
        sm0 += __shfl_xor_sync(0xffffffffu, sm0, 2);
        sm1 += __shfl_xor_sync(0xffffffffu, sm1, 1);
        sm1 += __shfl_xor_sync(0xffffffffu, sm1, 2);
        if ((lane & 3) == 0) {
            stat_sum[(g * 2 + h) * 16 + r]     = sm0;
            stat_sum[(g * 2 + h) * 16 + r + 8] = sm1;
        }
        #pragma unroll
        for (int i = 0; i < 16; ++i) {
            o[i][0] *= sc0; o[i][1] *= sc0;
            o[i][2] *= sc1; o[i][3] *= sc1;
        }
        __syncthreads();   // sums + P visible
        l0 = l0 * sc0 + stat_sum[(g * 2) * 16 + r]     + stat_sum[(g * 2 + 1) * 16 + r];
        l1 = l1 * sc1 + stat_sum[(g * 2) * 16 + r + 8] + stat_sum[(g * 2 + 1) * 16 + r + 8];

        // ---- PV: O(16 x 128h) += Phi*Vhi + Phi*Vlo + Plo*Vhi ----
        #pragma unroll
        for (int ks = 0; ks < 4; ++ks) {
            uint32_t ah[4], al[4];
            ldsm_x4(ah[0], ah[1], ah[2], ah[3], pa_hi + ks * 32);
            ldsm_x4(al[0], al[1], al[2], al[3], pa_lo + ks * 32);
            #pragma unroll
            for (int dc = 0; dc < 8; ++dc) {
                const uint32_t voff = (uint32_t)(ks * 16 * RS * 2 + dc * 32);
                uint32_t vh[4], vl[4];
                ldsm_x4t(vh[0], vh[1], vh[2], vh[3], vb_hi + voff);
                ldsm_x4t(vl[0], vl[1], vl[2], vl[3], vb_lo + voff);
                mma16816(o[2 * dc],     ah, vh[0], vh[1]);
                mma16816(o[2 * dc + 1], ah, vh[2], vh[3]);
                mma16816(o[2 * dc],     ah, vl[0], vl[1]);
                mma16816(o[2 * dc + 1], ah, vl[2], vl[3]);
                mma16816(o[2 * dc],     al, vh[0], vh[1]);
                mma16816(o[2 * dc + 1], al, vh[2], vh[3]);
            }
        }
    }

    // ---- epilogue ----
    const float inv0 = 1.0f / l0;
    const float inv1 = 1.0f / l1;
    const size_t row0 = (size_t)b * NSEQ + q0g + qr0 + r;
    const size_t row1 = row0 + 8;
    #pragma unroll
    for (int nt = 0; nt < 16; ++nt) {
        const int dcol = 128 * h + 8 * nt + 2 * (lane & 3);
        *(float2*)(out + row0 * DIM + dcol) = make_float2(o[nt][0] * inv0, o[nt][1] * inv0);
        *(float2*)(out + row1 * DIM + dcol) = make_float2(o[nt][2] * inv1, o[nt][3] * inv1);
    }
}

extern "C" void kernel_launch(void* const* d_in, const int* in_sizes, int n_in,
                              void* d_out, int out_size)
{
    (void)in_sizes; (void)n_in; (void)out_size;
    const float* X = (const float*)d_in[0];
    const int* len = (const int*)d_in[1];
    float* out = (float*)d_out;

    cudaFuncSetAttribute(attn_hmma, cudaFuncAttributeMaxDynamicSharedMemorySize, SM_TOTAL);
    dim3 grid(NSEQ / TQ, BATCH);   // (32, 16)
    attn_hmma<<<grid, THREADS, SM_TOTAL>>>(X, len, out);
}